// round 15
// baseline (speedup 1.0000x reference)
#include <cuda_runtime.h>
#include <cuda_bf16.h>
#include <math.h>

#define BB 256
#define HH 256
#define NLY 6
#define SS 128
#define G3 768
#define PITCH 40   // bf16 smem row pitch (conflict-free for ldmatrix)

struct Ptrs {
  const float *x, *Wih0, *Wih, *Whh, *bih, *bhh, *h0;
  const float *aW1, *aW2, *aW3, *aW4;
  const float *sdW1,*sdb1,*sdW2,*sdb2,*sdW3,*sdb3,*sdW4,*sdb4;
  const float *odW1,*odb1,*odW2,*odb2,*odW3,*odb3,*odW4,*odb4;
  float* out;
};

typedef unsigned long long u64;
typedef __nv_bfloat16 bf16;

// ---------------- fp32 scratch ----------------
__device__ __align__(16) float g_h[2][NLY][BB][HH];
__device__ __align__(16) float g_hpre[NLY][BB][HH];
__device__ __align__(16) float g_Gi[NLY][BB][G3];
__device__ __align__(16) float g_Gh[NLY][BB][G3];
__device__ __align__(16) float g_W2dT[NLY][512][512];
__device__ __align__(16) float g_W3d[NLY][512][512];
__device__ __align__(16) float g_W1T[NLY][256][256];
__device__ __align__(16) float g_Md[NLY][512][512];
__device__ __align__(16) float g_P[NLY][512][512];

// ---------------- bf16 hi/lo planes ----------------
__device__ __align__(16) bf16 g_xh[BB][16384],        g_xl[BB][16384];
__device__ __align__(16) bf16 g_W0h[G3][128],         g_W0l[G3][128];
__device__ __align__(16) bf16 g_WihH[NLY-1][G3][HH],  g_WihL[NLY-1][G3][HH];
__device__ __align__(16) bf16 g_WhhH[NLY][G3][HH],    g_WhhL[NLY][G3][HH];
__device__ __align__(16) bf16 g_Ph[NLY][512][512],    g_Pl[NLY][512][512];
__device__ __align__(16) bf16 g_W4h[NLY][256][512],   g_W4l[NLY][256][512];
__device__ __align__(16) bf16 g_h0h[NLY][HH],         g_h0l[NLY][HH];
__device__ __align__(16) bf16 g_hbh[2][NLY][BB][HH],  g_hbl[2][NLY][BB][HH];
__device__ __align__(16) bf16 g_hpreh[NLY][BB][HH],   g_hprel[NLY][BB][HH];
__device__ __align__(16) bf16 g_shh[NLY][BB][HH],     g_shl[NLY][BB][HH];
__device__ __align__(16) bf16 g_A3h[NLY][BB][512],    g_A3l[NLY][BB][512];

#define YSEQ_OFF 8388608ul
#define YONE_OFF 9437184ul

// ====================== f32x2 helpers (prep GEMMs only) =====================
__device__ __forceinline__ u64 dup2(float a) {
  u64 d; unsigned ai = __float_as_uint(a);
  asm("mov.b64 %0, {%1, %1};" : "=l"(d) : "r"(ai));
  return d;
}
__device__ __forceinline__ void fma2(u64& acc, u64 a, u64 b) {
  asm("fma.rn.f32x2 %0, %1, %2, %0;" : "+l"(acc) : "l"(a), "l"(b));
}
__device__ __forceinline__ void unpack2(u64 v, float& lo, float& hi) {
  unsigned l_, h_;
  asm("mov.b64 {%0, %1}, %2;" : "=r"(l_), "=r"(h_) : "l"(v));
  lo = __uint_as_float(l_); hi = __uint_as_float(h_);
}

__device__ __forceinline__ void gemm64(
    const float* __restrict__ A0, const float* __restrict__ A1, int lda,
    const float* __restrict__ W, int ldb, int K,
    u64 acc[4][2], float* As, float* Bs)
{
  const int t = threadIdx.x;
  const int ar = t >> 2, ak = (t & 3) << 1;
  const int tx = t & 15, ty = t >> 4;
  float2 ra, rb;
  auto loadT = [&](int k0) {
    int c = k0 + ak;
    const float* base = (c < 256) ? (A0 + c) : (A1 + (c - 256));
    ra = *(const float2*)(base + (size_t)ar * lda);
    rb = *(const float2*)(W + (size_t)ar * ldb + k0 + ak);
  };
  auto storeT = [&](int buf) {
    float* as = As + buf * 512;
    float* bs = Bs + buf * 512;
    as[ak*64 + ar] = ra.x; as[(ak+1)*64 + ar] = ra.y;
    bs[ak*64 + ar] = rb.x; bs[(ak+1)*64 + ar] = rb.y;
  };
  auto compute = [&](int buf) {
    const float* as = As + buf * 512 + ty * 4;
    const float* bs = Bs + buf * 512 + tx * 4;
#pragma unroll
    for (int kk = 0; kk < 8; kk++) {
      float4 a4v = *(const float4*)(as + kk * 64);
      ulonglong2 b2 = *(const ulonglong2*)(bs + kk * 64);
      u64 ad;
      ad = dup2(a4v.x); fma2(acc[0][0], ad, b2.x); fma2(acc[0][1], ad, b2.y);
      ad = dup2(a4v.y); fma2(acc[1][0], ad, b2.x); fma2(acc[1][1], ad, b2.y);
      ad = dup2(a4v.z); fma2(acc[2][0], ad, b2.x); fma2(acc[2][1], ad, b2.y);
      ad = dup2(a4v.w); fma2(acc[3][0], ad, b2.x); fma2(acc[3][1], ad, b2.y);
    }
  };
  const int nb = K >> 3;
  loadT(0); storeT(0); __syncthreads();
  for (int kb = 1; kb < nb; kb++) {
    loadT(kb << 3);
    compute((kb - 1) & 1);
    storeT(kb & 1);
    __syncthreads();
  }
  compute((nb - 1) & 1);
}

// ====================== bf16 split helpers ==================================
__device__ __forceinline__ void split1(float a, bf16& h, bf16& l) {
  h = __float2bfloat16_rn(a);
  l = __float2bfloat16_rn(a - __bfloat162float(h));
}
__device__ __forceinline__ void split2u(float a, float b, unsigned& hi, unsigned& lo) {
  bf16 ah, al, bh, bl;
  split1(a, ah, al); split1(b, bh, bl);
  hi = (unsigned)*(unsigned short*)&ah | ((unsigned)*(unsigned short*)&bh << 16);
  lo = (unsigned)*(unsigned short*)&al | ((unsigned)*(unsigned short*)&bl << 16);
}

// ====================== bf16x3 tensor-core GEMM core ========================
__device__ __forceinline__ unsigned s2u(const void* p) {
  return (unsigned)__cvta_generic_to_shared(p);
}
__device__ __forceinline__ void ldmx4(unsigned* r, unsigned a) {
  asm volatile("ldmatrix.sync.aligned.m8n8.x4.shared.b16 {%0,%1,%2,%3}, [%4];"
               : "=r"(r[0]), "=r"(r[1]), "=r"(r[2]), "=r"(r[3]) : "r"(a));
}
__device__ __forceinline__ void mma_bf16(float* c, const unsigned* a, const unsigned* b) {
  asm volatile("mma.sync.aligned.m16n8k16.row.col.f32.bf16.bf16.f32 "
               "{%0,%1,%2,%3}, {%4,%5,%6,%7}, {%8,%9}, {%0,%1,%2,%3};"
               : "+f"(c[0]), "+f"(c[1]), "+f"(c[2]), "+f"(c[3])
               : "r"(a[0]), "r"(a[1]), "r"(a[2]), "r"(a[3]), "r"(b[0]), "r"(b[1]));
}
__device__ __forceinline__ void cpa16(unsigned dst, const void* src) {
  asm volatile("cp.async.cg.shared.global [%0], [%1], 16;" :: "r"(dst), "l"(src));
}
#define CP_COMMIT() asm volatile("cp.async.commit_group;" ::: "memory")
#define CP_WAIT2()  asm volatile("cp.async.wait_group 2;" ::: "memory")

// MT x 64 tile, 2*MT threads (MT/16 m-warps x 2 n-warps, warp = 32m x 32n).
// 3-stage cp.async pipeline over 32-wide K chunks. TERM-MAJOR MMA ordering:
// per kk, issue all 8 independent hh MMAs, then 8 hl, then 8 lh (ILP=8).
template<int MT>
__device__ void mma_tileb(
    const bf16* __restrict__ Ah, const bf16* __restrict__ Al,
    const bf16* __restrict__ A1h, const bf16* __restrict__ A1l, int lda,
    const bf16* __restrict__ Wh, const bf16* __restrict__ Wl, int ldw, int K,
    float c[2][4][4], bf16* sm)
{
  constexpr int APL = MT * PITCH;            // A plane elems
  constexpr int WPL = 64 * PITCH;            // W plane elems
  constexpr int BUF_E = 2*APL + 2*WPL;       // elems per ring buffer
  const int t = threadIdx.x;                 // 0..2*MT-1
  const int lane = t & 31, wid = t >> 5;
  const int wm = wid >> 1, wn = wid & 1;
  const int arow = lane & 15, acg = (lane >> 4) << 3;
  const int bq = lane >> 3, brr = lane & 7;
  const int bn_base = wn*32 + ((bq >> 1) << 3) + brr;
  const int bkoff = (bq & 1) << 3;
  const unsigned aoff0 = (unsigned)((wm*32 + arow) * PITCH + acg) * 2;
  const unsigned boff0 = (unsigned)(bn_base * PITCH + bkoff) * 2;
  const unsigned base = s2u(sm);

  auto issueChunk = [&](int kb, int buf) {
    unsigned sb = base + (unsigned)(buf * BUF_E) * 2;
#pragma unroll
    for (int i = 0; i < 2; i++) {              // A: MT*4 slots
      int slot = t + i * (2*MT);
      int row = slot >> 2, cg8 = (slot & 3) << 3;
      int cidx = kb + cg8;
      const bf16 *bh_, *bl_; int cc;
      if (cidx < 256) { bh_ = Ah;  bl_ = Al;  cc = cidx; }
      else            { bh_ = A1h; bl_ = A1l; cc = cidx - 256; }
      size_t ao = (size_t)row * lda + cc;
      unsigned dst = sb + (unsigned)(row * PITCH + cg8) * 2;
      cpa16(dst, bh_ + ao);
      cpa16(dst + APL*2, bl_ + ao);
    }
#pragma unroll
    for (int i = 0; i < 256/(2*MT); i++) {     // W: 256 slots
      int slot = t + i * (2*MT);
      int row = slot >> 2, cg8 = (slot & 3) << 3;
      size_t wo = (size_t)row * ldw + kb + cg8;
      unsigned wdst = sb + (unsigned)(2*APL)*2 + (unsigned)(row * PITCH + cg8) * 2;
      cpa16(wdst, Wh + wo);
      cpa16(wdst + WPL*2, Wl + wo);
    }
  };
  auto compute = [&](int buf) {
    unsigned b0 = base + (unsigned)(buf * BUF_E) * 2;
    unsigned uAh = b0, uAl = b0 + APL*2, uWh = b0 + 2*APL*2, uWl = b0 + 2*APL*2 + WPL*2;
#pragma unroll
    for (int kk = 0; kk < 32; kk += 16) {
      unsigned ah[2][4], al[2][4], bh[8], bl[8];
#pragma unroll
      for (int mi = 0; mi < 2; mi++) {
        unsigned off = aoff0 + (unsigned)(mi*16*PITCH + kk) * 2;
        ldmx4(ah[mi], uAh + off);
        ldmx4(al[mi], uAl + off);
      }
#pragma unroll
      for (int half = 0; half < 2; half++) {
        unsigned off = boff0 + (unsigned)(half*16*PITCH + kk) * 2;
        ldmx4(bh + half*4, uWh + off);
        ldmx4(bl + half*4, uWl + off);
      }
      // term-major: 8 independent MMAs per group, 3 groups (hh, hl, lh)
#pragma unroll
      for (int mi = 0; mi < 2; mi++)
#pragma unroll
        for (int ni = 0; ni < 4; ni++)
          mma_bf16(c[mi][ni], ah[mi], bh + ni*2);
#pragma unroll
      for (int mi = 0; mi < 2; mi++)
#pragma unroll
        for (int ni = 0; ni < 4; ni++)
          mma_bf16(c[mi][ni], ah[mi], bl + ni*2);
#pragma unroll
      for (int mi = 0; mi < 2; mi++)
#pragma unroll
        for (int ni = 0; ni < 4; ni++)
          mma_bf16(c[mi][ni], al[mi], bh + ni*2);
    }
  };

  const int nb = K >> 5;                 // always >= 4
  issueChunk(0, 0);  CP_COMMIT();
  issueChunk(32, 1); CP_COMMIT();
  issueChunk(64, 2); CP_COMMIT();
  for (int k = 0; k < nb; k++) {
    CP_WAIT2();
    __syncthreads();
    compute(k % 3);
    __syncthreads();
    int kn = k + 3;
    if (kn < nb) issueChunk(kn << 5, kn % 3);
    CP_COMMIT();
  }
}

#define SM_DYN64  (3 * (2*64*PITCH + 2*64*PITCH) * 2)    // 61440 B
#define SM_DYN128 (3 * (2*128*PITCH + 2*64*PITCH) * 2)   // 92160 B

// ---------------------------------------------------------------------------
// Prep kernels
// ---------------------------------------------------------------------------
__global__ void prep_a(Ptrs P) {
  int i = blockIdx.x * 256 + threadIdx.x;
  if (i < NLY * 512 * 512) {
    int l = i >> 18; int r = i & 262143; int row = r >> 9; int col = r & 511;
    {
      int cc = row, g = col >> 7, j = col & 127;
      int v = ((cc & 127) << 2) | (cc >> 7);
      float val = ((v >> 7) == g) ? P.aW2[((size_t)l*128 + j)*128 + (v & 127)] : 0.f;
      g_W2dT[l][cc][col] = val;
    }
    {
      int g = row >> 7, j = row & 127, cc = col;
      int v = ((cc & 127) << 2) | (cc >> 7);
      float val = ((v >> 7) == g) ? P.aW3[((size_t)l*128 + j)*128 + (v & 127)] : 0.f;
      g_W3d[l][row][col] = val;
    }
  }
  if (i < NLY * 256 * 256) {
    int l = i >> 16; int r = i & 65535; int c1 = r >> 8; int k = r & 255;
    g_W1T[l][k][c1] = P.aW1[(size_t)l*65536 + (size_t)c1*256 + k];
  }
}

__global__ void sp_all(Ptrs P) {
  int i = blockIdx.x * 256 + threadIdx.x;
  if (i < BB*16384)        split1(P.x[i],    ((bf16*)g_xh)[i],   ((bf16*)g_xl)[i]);
  if (i < G3*128)          split1(P.Wih0[i], ((bf16*)g_W0h)[i],  ((bf16*)g_W0l)[i]);
  if (i < (NLY-1)*G3*HH)   split1(P.Wih[i],  ((bf16*)g_WihH)[i], ((bf16*)g_WihL)[i]);
  if (i < NLY*G3*HH)       split1(P.Whh[i],  ((bf16*)g_WhhH)[i], ((bf16*)g_WhhL)[i]);
  if (i < NLY*256*512)     split1(P.aW4[i],  ((bf16*)g_W4h)[i],  ((bf16*)g_W4l)[i]);
  if (i < NLY*HH)          split1(P.h0[i],   ((bf16*)g_h0h)[i],  ((bf16*)g_h0l)[i]);
}

__global__ void __launch_bounds__(256, 4) prep_md() {
  __shared__ __align__(16) float As[1024], Bs[1024];
  int l = blockIdx.y;
  int i = blockIdx.x;
  int m0 = (i & 7) << 6, n0 = (i >> 3) << 6;
  const float* A0 = &g_W3d[l][m0][0];
  const float* W  = &g_W2dT[l][n0][0];
  u64 acc[4][2] = {};
  gemm64(A0, A0 + 256, 512, W, 512, 512, acc, As, Bs);
  int tx = threadIdx.x & 15, ty = threadIdx.x >> 4;
#pragma unroll
  for (int r = 0; r < 4; r++) {
    float v0,v1,v2,v3;
    unpack2(acc[r][0], v0, v1); unpack2(acc[r][1], v2, v3);
    *(float4*)(&g_Md[l][m0 + ty*4 + r][n0 + tx*4]) = make_float4(v0,v1,v2,v3);
  }
}

__global__ void __launch_bounds__(256, 4) prep_p() {
  __shared__ __align__(16) float As[1024], Bs[1024];
  int l = blockIdx.y;
  int i = blockIdx.x;
  int m0 = (i & 7) << 6;
  int nt = i >> 3;
  int half = nt >> 2;
  const float* A0 = &g_Md[l][m0][half * 256];
  const float* W  = &g_W1T[l][(nt & 3) * 64][0];
  u64 acc[4][2] = {};
  gemm64(A0, A0, 512, W, 256, 256, acc, As, Bs);
  int tx = threadIdx.x & 15, ty = threadIdx.x >> 4;
#pragma unroll
  for (int r = 0; r < 4; r++) {
    float v0,v1,v2,v3;
    unpack2(acc[r][0], v0, v1); unpack2(acc[r][1], v2, v3);
    *(float4*)(&g_P[l][m0 + ty*4 + r][nt*64 + tx*4]) = make_float4(v0,v1,v2,v3);
  }
}

__global__ void sp_P() {
  int i = blockIdx.x * 256 + threadIdx.x;
  if (i < NLY*512*512) split1(((float*)g_P)[i], ((bf16*)g_Ph)[i], ((bf16*)g_Pl)[i]);
}

// ---------------------------------------------------------------------------
// Stage 1 (tensor, 128x64 tiles): Gi = inp @ Wih^T ; Gh = h_prev @ Whh^T.
// grid(48, nA), 256 thr.
// ---------------------------------------------------------------------------
__global__ void __launch_bounds__(256) stage1_k(Ptrs P, int w, int lmin, int pp) {
  extern __shared__ __align__(16) bf16 sm[];
  int l = lmin + blockIdx.y, ts = w - l;
  int i = blockIdx.x;
  int which = (i >= 24); i -= which * 24;
  int m0 = (i & 1) << 7, n0 = (i >> 1) << 6;
  const bf16 *Ah, *Al, *Wh, *Wl; int lda, K, ldw; float* out;
  if (!which) {
    if (l == 0) { Ah = &g_xh[m0][ts*128]; Al = &g_xl[m0][ts*128]; lda = 16384; K = 128;
                  Wh = &g_W0h[n0][0]; Wl = &g_W0l[n0][0]; ldw = 128; }
    else        { Ah = &g_hbh[pp][l-1][m0][0]; Al = &g_hbl[pp][l-1][m0][0]; lda = HH; K = HH;
                  Wh = &g_WihH[l-1][n0][0]; Wl = &g_WihL[l-1][n0][0]; ldw = HH; }
    out = &g_Gi[l][0][0];
  } else {
    if (ts == 0) { Ah = &g_h0h[l][0]; Al = &g_h0l[l][0]; lda = 0; }
    else         { Ah = &g_hbh[pp][l][m0][0]; Al = &g_hbl[pp][l][m0][0]; lda = HH; }
    K = HH; Wh = &g_WhhH[l][n0][0]; Wl = &g_WhhL[l][n0][0]; ldw = HH;
    out = &g_Gh[l][0][0];
  }
  float c[2][4][4] = {};
  mma_tileb<128>(Ah, Al, Ah, Al, lda, Wh, Wl, ldw, K, c, sm);
  int lane = threadIdx.x & 31, wid = threadIdx.x >> 5;
  int wm = wid >> 1, wn = wid & 1;
#pragma unroll
  for (int mi = 0; mi < 2; mi++) {
    int r0 = m0 + wm*32 + mi*16 + (lane >> 2);
#pragma unroll
    for (int ni = 0; ni < 4; ni++) {
      int col = n0 + wn*32 + ni*8 + 2*(lane & 3);
      *(float2*)(out + (size_t)r0 * G3 + col)       = make_float2(c[mi][ni][0], c[mi][ni][1]);
      *(float2*)(out + (size_t)(r0 + 8) * G3 + col) = make_float2(c[mi][ni][2], c[mi][ni][3]);
    }
  }
}

// ---------------------------------------------------------------------------
// Stage 2: gates -> hpre (fp32 + bf16 planes), bitonic sort -> sh planes.
// ---------------------------------------------------------------------------
__global__ void __launch_bounds__(256) gatesort_k(Ptrs P, int w, int lmin, int pp) {
  int l = lmin + blockIdx.y, t = w - l;
  int warp = threadIdx.x >> 5, lane = threadIdx.x & 31;
  int b = blockIdx.x * 8 + warp;
  __shared__ float vbuf[8][256];
  float* v = vbuf[warp];
  const float* bi = P.bih + l * G3;
  const float* bh = P.bhh + l * G3;
#pragma unroll
  for (int q = 0; q < 8; q++) {
    int j = lane + (q << 5);
    float gi0 = g_Gi[l][b][j]      + bi[j];
    float gi1 = g_Gi[l][b][j+256]  + bi[j+256];
    float gi2 = g_Gi[l][b][j+512]  + bi[j+512];
    float gh0 = g_Gh[l][b][j]      + bh[j];
    float gh1 = g_Gh[l][b][j+256]  + bh[j+256];
    float gh2 = g_Gh[l][b][j+512]  + bh[j+512];
    float r = 1.f / (1.f + expf(-(gi0 + gh0)));
    float z = 1.f / (1.f + expf(-(gi1 + gh1)));
    float n = tanhf(gi2 + r * gh2);
    float hp = (t == 0) ? P.h0[l * HH + j] : g_h[pp][l][b][j];
    float hv = (1.f - z) * n + z * hp;
    g_hpre[l][b][j] = hv;
    split1(hv, g_hpreh[l][b][j], g_hprel[l][b][j]);
    v[j] = hv;
  }
  __syncwarp();
  for (int k = 2; k <= 256; k <<= 1) {
    for (int jj = k >> 1; jj > 0; jj >>= 1) {
#pragma unroll
      for (int q = 0; q < 8; q++) {
        int idx = lane + (q << 5);
        int ixj = idx ^ jj;
        if (ixj > idx) {
          float a = v[idx], cc = v[ixj];
          bool up = ((idx & k) == 0);
          if ((a > cc) == up) { v[idx] = cc; v[ixj] = a; }
        }
      }
      __syncwarp();
    }
  }
#pragma unroll
  for (int q = 0; q < 8; q++) {
    int j = lane + (q << 5);
    split1(v[j], g_shh[l][b][j], g_shl[l][b][j]);
  }
}

// ---------------------------------------------------------------------------
// Stage 3 (tensor, fused a1+a2+a3): A3 = relu([hpre|sh] @ P^T). grid(32, nA)
// ---------------------------------------------------------------------------
__global__ void __launch_bounds__(128) attn_k(int lmin) {
  extern __shared__ __align__(16) bf16 sm[];
  int l = lmin + blockIdx.y;
  int i = blockIdx.x;
  int m0 = (i & 3) << 6, n0 = (i >> 2) << 6;
  float c[2][4][4] = {};
  mma_tileb<64>(&g_hpreh[l][m0][0], &g_hprel[l][m0][0],
                &g_shh[l][m0][0],   &g_shl[l][m0][0], 256,
                &g_Ph[l][n0][0],    &g_Pl[l][n0][0], 512, 512, c, sm);
  int lane = threadIdx.x & 31, wid = threadIdx.x >> 5;
  int wm = wid >> 1, wn = wid & 1;
#pragma unroll
  for (int mi = 0; mi < 2; mi++) {
    int r0 = m0 + wm*32 + mi*16 + (lane >> 2);
#pragma unroll
    for (int ni = 0; ni < 4; ni++) {
      int col = n0 + wn*32 + ni*8 + 2*(lane & 3);
#pragma unroll
      for (int half = 0; half < 2; half++) {
        int row = r0 + half*8;
        float v0 = fmaxf(c[mi][ni][half*2], 0.f);
        float v1 = fmaxf(c[mi][ni][half*2+1], 0.f);
        unsigned hi, lo; split2u(v0, v1, hi, lo);
        *(unsigned*)(&g_A3h[l][row][col]) = hi;
        *(unsigned*)(&g_A3l[l][row][col]) = lo;
      }
    }
  }
}

// ---------------------------------------------------------------------------
// Stage 4 (tensor): a4 = A3 @ W4^T ; h = hpre * sigmoid(a4). grid(16, nA)
// ---------------------------------------------------------------------------
__global__ void __launch_bounds__(128) a4_k(Ptrs P, int w, int lmin, int p) {
  extern __shared__ __align__(16) bf16 sm[];
  int l = lmin + blockIdx.y, ts = w - l;
  int i = blockIdx.x;
  int m0 = (i & 3) << 6, n0 = (i >> 2) << 6;
  float c[2][4][4] = {};
  mma_tileb<64>(&g_A3h[l][m0][0], &g_A3l[l][m0][0],
                &g_A3h[l][m0][256], &g_A3l[l][m0][256], 512,
                &g_W4h[l][n0][0], &g_W4l[l][n0][0], 512, 512, c, sm);
  int lane = threadIdx.x & 31, wid = threadIdx.x >> 5;
  int wm = wid >> 1, wn = wid & 1;
#pragma unroll
  for (int mi = 0; mi < 2; mi++) {
    int r0 = m0 + wm*32 + mi*16 + (lane >> 2);
#pragma unroll
    for (int ni = 0; ni < 4; ni++) {
      int col = n0 + wn*32 + ni*8 + 2*(lane & 3);
#pragma unroll
      for (int half = 0; half < 2; half++) {
        int row = r0 + half*8;
        float va = c[mi][ni][half*2], vb = c[mi][ni][half*2+1];
        float2 hp = *(float2*)(&g_hpre[l][row][col]);
        float h0v = hp.x * (1.f / (1.f + expf(-va)));
        float h1v = hp.y * (1.f / (1.f + expf(-vb)));
        *(float2*)(&g_h[p][l][row][col]) = make_float2(h0v, h1v);
        unsigned hi, lo; split2u(h0v, h1v, hi, lo);
        *(unsigned*)(&g_hbh[p][l][row][col]) = hi;
        *(unsigned*)(&g_hbl[p][l][row][col]) = lo;
        if (l == NLY - 1)
          *(float2*)(P.out + (size_t)row * 32768 + (size_t)ts * 256 + col) = make_float2(h0v, h1v);
      }
    }
  }
}

// ---------------------------------------------------------------------------
__global__ void seqdec_kernel(Ptrs P) {
  int idx = blockIdx.x * blockDim.x + threadIdx.x;
  int b = idx >> 7, s = idx & 127;
  const float* e = P.out + (size_t)b * 32768 + (size_t)s * 256;
  float a1[8][4], a2[8][4], a3[8][4];
#pragma unroll
  for (int g = 0; g < 8; g++)
#pragma unroll
    for (int o = 0; o < 4; o++) {
      float sum = P.sdb1[o];
#pragma unroll
      for (int m = 0; m < 32; m++) sum += e[g*32+m] * P.sdW1[o*32+m];
      a1[g][o] = sum;
    }
#pragma unroll
  for (int i = 0; i < 8; i++)
#pragma unroll
    for (int o = 0; o < 4; o++) {
      float sum = P.sdb2[o];
#pragma unroll
      for (int j = 0; j < 4; j++) {
        int f = i*4 + j;
        sum += a1[f & 7][f >> 3] * P.sdW2[o*4+j];
      }
      a2[i][o] = sum;
    }
#pragma unroll
  for (int i = 0; i < 8; i++)
#pragma unroll
    for (int o = 0; o < 4; o++) {
      float sum = P.sdb3[o];
#pragma unroll
      for (int j = 0; j < 4; j++) {
        int f = i*4 + j;
        sum += a2[f & 7][f >> 3] * P.sdW3[o*4+j];
      }
      a3[i][o] = sum;
    }
#pragma unroll
  for (int o = 0; o < 4; o++)
#pragma unroll
    for (int wv = 0; wv < 8; wv++) {
      float sum = P.sdb4[wv];
#pragma unroll
      for (int g = 0; g < 8; g++) {
        int f = o*8 + g;
        sum += a3[f >> 2][f & 3] * P.sdW4[wv*8+g];
      }
      P.out[YSEQ_OFF + (size_t)b * 4096 + (size_t)(s*8 + wv) * 4 + o] = sum;
    }
}

// ---------------------------------------------------------------------------
__global__ void onedec_kernel(Ptrs P) {
  int b = blockIdx.x;
  __shared__ float acc[10][4];
  int tid = threadIdx.x;
  if (tid < 10) {
    int s = 118 + tid;
    const float* e = P.out + (size_t)b * 32768 + (size_t)s * 256;
    float o1[8][4], o2[8][4], o3[8][4];
#pragma unroll
    for (int g = 0; g < 8; g++)
#pragma unroll
      for (int o = 0; o < 4; o++) {
        float sum = P.odb1[o];
#pragma unroll
        for (int m = 0; m < 32; m++) sum += e[g*32+m] * P.odW1[o*32+m];
        o1[g][o] = sum;
      }
#pragma unroll
    for (int i = 0; i < 8; i++)
#pragma unroll
      for (int o = 0; o < 4; o++) {
        float sum = P.odb2[o];
#pragma unroll
        for (int j = 0; j < 4; j++) {
          int f = i*4 + j;
          sum += o1[f & 7][f >> 3] * P.odW2[o*4+j];
        }
        o2[i][o] = sum;
      }
#pragma unroll
    for (int i = 0; i < 8; i++)
#pragma unroll
      for (int o = 0; o < 4; o++) {
        float sum = P.odb3[o];
#pragma unroll
        for (int j = 0; j < 4; j++) {
          int f = i*4 + j;
          sum += o2[f & 7][f >> 3] * P.odW3[o*4+j];
        }
        o3[i][o] = fmaxf(sum, 0.f);
      }
#pragma unroll
    for (int c = 0; c < 4; c++) {
      float sum = P.odb4[c];
#pragma unroll
      for (int f = 0; f < 32; f++) sum += o3[f >> 2][f & 3] * P.odW4[c*32+f];
      acc[tid][c] = 1.f / (1.f + expf(-sum));
    }
  }
  __syncthreads();
  if (tid < 4) {
    float s = 0.f;
#pragma unroll
    for (int i = 0; i < 10; i++) s += acc[i][tid];
    P.out[YONE_OFF + (size_t)b * 4 + tid] = s * 0.1f;
  }
}

// ---------------------------------------------------------------------------
extern "C" void kernel_launch(void* const* d_in, const int* in_sizes, int n_in,
                              void* d_out, int out_size) {
  (void)in_sizes; (void)n_in; (void)out_size;
  Ptrs P;
  P.x    = (const float*)d_in[0];
  P.Wih0 = (const float*)d_in[1];
  P.Wih  = (const float*)d_in[2];
  P.Whh  = (const float*)d_in[3];
  P.bih  = (const float*)d_in[4];
  P.bhh  = (const float*)d_in[5];
  P.h0   = (const float*)d_in[6];
  P.aW1  = (const float*)d_in[7];
  P.aW2  = (const float*)d_in[8];
  P.aW3  = (const float*)d_in[9];
  P.aW4  = (const float*)d_in[10];
  P.sdW1 = (const float*)d_in[11];
  P.sdb1 = (const float*)d_in[12];
  P.sdW2 = (const float*)d_in[13];
  P.sdb2 = (const float*)d_in[14];
  P.sdW3 = (const float*)d_in[15];
  P.sdb3 = (const float*)d_in[16];
  P.sdW4 = (const float*)d_in[17];
  P.sdb4 = (const float*)d_in[18];
  P.odW1 = (const float*)d_in[19];
  P.odb1 = (const float*)d_in[20];
  P.odW2 = (const float*)d_in[21];
  P.odb2 = (const float*)d_in[22];
  P.odW3 = (const float*)d_in[23];
  P.odb3 = (const float*)d_in[24];
  P.odW4 = (const float*)d_in[25];
  P.odb4 = (const float*)d_in[26];
  P.out  = (float*)d_out;

  static int attr_done = 0;
  if (!attr_done) {
    cudaFuncSetAttribute(stage1_k, cudaFuncAttributeMaxDynamicSharedMemorySize, SM_DYN128);
    cudaFuncSetAttribute(attn_k,   cudaFuncAttributeMaxDynamicSharedMemorySize, SM_DYN64);
    cudaFuncSetAttribute(a4_k,     cudaFuncAttributeMaxDynamicSharedMemorySize, SM_DYN64);
    attr_done = 1;
  }

  prep_a<<<6144, 256>>>(P);
  sp_all<<<16384, 256>>>(P);
  prep_md<<<dim3(64, NLY), 256>>>();

  for (int w = 0; w < SS + NLY - 1; w++) {
    int lmin = w - (SS - 1); if (lmin < 0) lmin = 0;
    int lmax = (w < NLY - 1) ? w : NLY - 1;
    int nA = lmax - lmin + 1;
    int pp = (w + 1) & 1;
    int p  = w & 1;
    stage1_k<<<dim3(48, nA), 256, SM_DYN128>>>(P, w, lmin, pp);
    if (w == 0) {
      prep_p<<<dim3(64, NLY), 256>>>();
      sp_P<<<6144, 256>>>();
    }
    gatesort_k<<<dim3(32, nA), 256>>>(P, w, lmin, pp);
    attn_k<<<dim3(32, nA), 128, SM_DYN64>>>(lmin);
    a4_k<<<dim3(16, nA), 128, SM_DYN64>>>(P, w, lmin, p);
  }

  seqdec_kernel<<<128, 256>>>(P);
  onedec_kernel<<<256, 32>>>(P);
}

// round 16
// speedup vs baseline: 1.1779x; 1.1779x over previous
#include <cuda_runtime.h>
#include <cuda_fp16.h>
#include <math.h>

#define BB 256
#define HH 256
#define NLY 6
#define SS 128
#define G3 768
#define PITCH 40   // fp16 smem row pitch (conflict-free for ldmatrix)

struct Ptrs {
  const float *x, *Wih0, *Wih, *Whh, *bih, *bhh, *h0;
  const float *aW1, *aW2, *aW3, *aW4;
  const float *sdW1,*sdb1,*sdW2,*sdb2,*sdW3,*sdb3,*sdW4,*sdb4;
  const float *odW1,*odb1,*odW2,*odb2,*odW3,*odb3,*odW4,*odb4;
  float* out;
};

typedef unsigned long long u64;

// ---------------- fp32 scratch ----------------
__device__ __align__(16) float g_h[2][NLY][BB][HH];
__device__ __align__(16) float g_hpre[NLY][BB][HH];
__device__ __align__(16) float g_Gi[NLY][BB][G3];
__device__ __align__(16) float g_Gh[NLY][BB][G3];
__device__ __align__(16) float g_W2dT[NLY][512][512];
__device__ __align__(16) float g_W3d[NLY][512][512];
__device__ __align__(16) float g_W1T[NLY][256][256];
__device__ __align__(16) float g_Md[NLY][512][512];
__device__ __align__(16) float g_P[NLY][512][512];

// ---------------- fp16 planes: activations single, weights hi/lo ----------
__device__ __align__(16) half g_xf[BB][16384];
__device__ __align__(16) half g_W0h[G3][128],         g_W0l[G3][128];
__device__ __align__(16) half g_WihH[NLY-1][G3][HH],  g_WihL[NLY-1][G3][HH];
__device__ __align__(16) half g_WhhH[NLY][G3][HH],    g_WhhL[NLY][G3][HH];
__device__ __align__(16) half g_Ph[NLY][512][512],    g_Pl[NLY][512][512];
__device__ __align__(16) half g_W4h[NLY][256][512],   g_W4l[NLY][256][512];
__device__ __align__(16) half g_h0f[NLY][HH];
__device__ __align__(16) half g_hbf[2][NLY][BB][HH];
__device__ __align__(16) half g_hpref[NLY][BB][HH];
__device__ __align__(16) half g_shf[NLY][BB][HH];
__device__ __align__(16) half g_A3f[NLY][BB][512];

#define YSEQ_OFF 8388608ul
#define YONE_OFF 9437184ul

// ====================== f32x2 helpers (prep GEMMs only) =====================
__device__ __forceinline__ u64 dup2(float a) {
  u64 d; unsigned ai = __float_as_uint(a);
  asm("mov.b64 %0, {%1, %1};" : "=l"(d) : "r"(ai));
  return d;
}
__device__ __forceinline__ void fma2(u64& acc, u64 a, u64 b) {
  asm("fma.rn.f32x2 %0, %1, %2, %0;" : "+l"(acc) : "l"(a), "l"(b));
}
__device__ __forceinline__ void unpack2(u64 v, float& lo, float& hi) {
  unsigned l_, h_;
  asm("mov.b64 {%0, %1}, %2;" : "=r"(l_), "=r"(h_) : "l"(v));
  lo = __uint_as_float(l_); hi = __uint_as_float(h_);
}

__device__ __forceinline__ void gemm64(
    const float* __restrict__ A0, const float* __restrict__ A1, int lda,
    const float* __restrict__ W, int ldb, int K,
    u64 acc[4][2], float* As, float* Bs)
{
  const int t = threadIdx.x;
  const int ar = t >> 2, ak = (t & 3) << 1;
  const int tx = t & 15, ty = t >> 4;
  float2 ra, rb;
  auto loadT = [&](int k0) {
    int c = k0 + ak;
    const float* base = (c < 256) ? (A0 + c) : (A1 + (c - 256));
    ra = *(const float2*)(base + (size_t)ar * lda);
    rb = *(const float2*)(W + (size_t)ar * ldb + k0 + ak);
  };
  auto storeT = [&](int buf) {
    float* as = As + buf * 512;
    float* bs = Bs + buf * 512;
    as[ak*64 + ar] = ra.x; as[(ak+1)*64 + ar] = ra.y;
    bs[ak*64 + ar] = rb.x; bs[(ak+1)*64 + ar] = rb.y;
  };
  auto compute = [&](int buf) {
    const float* as = As + buf * 512 + ty * 4;
    const float* bs = Bs + buf * 512 + tx * 4;
#pragma unroll
    for (int kk = 0; kk < 8; kk++) {
      float4 a4v = *(const float4*)(as + kk * 64);
      ulonglong2 b2 = *(const ulonglong2*)(bs + kk * 64);
      u64 ad;
      ad = dup2(a4v.x); fma2(acc[0][0], ad, b2.x); fma2(acc[0][1], ad, b2.y);
      ad = dup2(a4v.y); fma2(acc[1][0], ad, b2.x); fma2(acc[1][1], ad, b2.y);
      ad = dup2(a4v.z); fma2(acc[2][0], ad, b2.x); fma2(acc[2][1], ad, b2.y);
      ad = dup2(a4v.w); fma2(acc[3][0], ad, b2.x); fma2(acc[3][1], ad, b2.y);
    }
  };
  const int nb = K >> 3;
  loadT(0); storeT(0); __syncthreads();
  for (int kb = 1; kb < nb; kb++) {
    loadT(kb << 3);
    compute((kb - 1) & 1);
    storeT(kb & 1);
    __syncthreads();
  }
  compute((nb - 1) & 1);
}

// ====================== fp16 helpers ==================================
__device__ __forceinline__ void splitw(float a, half& h, half& l) {
  h = __float2half_rn(a);
  l = __float2half_rn(a - __half2float(h));
}
__device__ __forceinline__ unsigned pack2h(float a, float b) {
  __half2 h2 = __floats2half2_rn(a, b);
  return *(unsigned*)&h2;
}

// ====================== fp16x2 tensor-core GEMM core ========================
__device__ __forceinline__ unsigned s2u(const void* p) {
  return (unsigned)__cvta_generic_to_shared(p);
}
__device__ __forceinline__ void ldmx4(unsigned* r, unsigned a) {
  asm volatile("ldmatrix.sync.aligned.m8n8.x4.shared.b16 {%0,%1,%2,%3}, [%4];"
               : "=r"(r[0]), "=r"(r[1]), "=r"(r[2]), "=r"(r[3]) : "r"(a));
}
__device__ __forceinline__ void mma_f16(float* c, const unsigned* a, const unsigned* b) {
  asm volatile("mma.sync.aligned.m16n8k16.row.col.f32.f16.f16.f32 "
               "{%0,%1,%2,%3}, {%4,%5,%6,%7}, {%8,%9}, {%0,%1,%2,%3};"
               : "+f"(c[0]), "+f"(c[1]), "+f"(c[2]), "+f"(c[3])
               : "r"(a[0]), "r"(a[1]), "r"(a[2]), "r"(a[3]), "r"(b[0]), "r"(b[1]));
}
__device__ __forceinline__ void cpa16(unsigned dst, const void* src) {
  asm volatile("cp.async.cg.shared.global [%0], [%1], 16;" :: "r"(dst), "l"(src));
}
#define CP_COMMIT() asm volatile("cp.async.commit_group;" ::: "memory")
#define CP_WAIT2()  asm volatile("cp.async.wait_group 2;" ::: "memory")

// MT x 64 tile, 2*MT threads (MT/16 m-warps x 2 n-warps, warp = 32m x 32n).
// fp16 2-term: C = A @ (Wh + Wl). A single fp16 plane; W hi/lo fp16 planes.
// 3-stage cp.async pipeline over 32-wide K chunks; term-major MMA (ILP=8).
// A concat: col c<256 from Af, else A1f at c-256. lda in elems (0=broadcast).
template<int MT>
__device__ void mma_tileb(
    const half* __restrict__ Af, const half* __restrict__ A1f, int lda,
    const half* __restrict__ Wh, const half* __restrict__ Wl, int ldw, int K,
    float c[2][4][4], half* sm)
{
  constexpr int APL = MT * PITCH;            // A plane elems
  constexpr int WPL = 64 * PITCH;            // W plane elems
  constexpr int BUF_E = APL + 2*WPL;         // elems per ring buffer
  const int t = threadIdx.x;                 // 0..2*MT-1
  const int lane = t & 31, wid = t >> 5;
  const int wm = wid >> 1, wn = wid & 1;
  const int arow = lane & 15, acg = (lane >> 4) << 3;
  const int bq = lane >> 3, brr = lane & 7;
  const int bn_base = wn*32 + ((bq >> 1) << 3) + brr;
  const int bkoff = (bq & 1) << 3;
  const unsigned aoff0 = (unsigned)((wm*32 + arow) * PITCH + acg) * 2;
  const unsigned boff0 = (unsigned)(bn_base * PITCH + bkoff) * 2;
  const unsigned base = s2u(sm);

  auto issueChunk = [&](int kb, int buf) {
    unsigned sb = base + (unsigned)(buf * BUF_E) * 2;
#pragma unroll
    for (int i = 0; i < 2; i++) {              // A: MT*4 quads
      int slot = t + i * (2*MT);
      int row = slot >> 2, cg8 = (slot & 3) << 3;
      int cidx = kb + cg8;
      const half* src; int cc;
      if (cidx < 256) { src = Af;  cc = cidx; }
      else            { src = A1f; cc = cidx - 256; }
      cpa16(sb + (unsigned)(row * PITCH + cg8) * 2,
            src + (size_t)row * lda + cc);
    }
#pragma unroll
    for (int i = 0; i < 256/(2*MT); i++) {     // W: 256 quads per plane
      int slot = t + i * (2*MT);
      int row = slot >> 2, cg8 = (slot & 3) << 3;
      size_t wo = (size_t)row * ldw + kb + cg8;
      unsigned wdst = sb + (unsigned)APL*2 + (unsigned)(row * PITCH + cg8) * 2;
      cpa16(wdst, Wh + wo);
      cpa16(wdst + WPL*2, Wl + wo);
    }
  };
  auto compute = [&](int buf) {
    unsigned b0 = base + (unsigned)(buf * BUF_E) * 2;
    unsigned uA = b0, uWh = b0 + APL*2, uWl = b0 + APL*2 + WPL*2;
#pragma unroll
    for (int kk = 0; kk < 32; kk += 16) {
      unsigned a[2][4], bh[8], bl[8];
#pragma unroll
      for (int mi = 0; mi < 2; mi++)
        ldmx4(a[mi], uA + aoff0 + (unsigned)(mi*16*PITCH + kk) * 2);
#pragma unroll
      for (int hf = 0; hf < 2; hf++) {
        unsigned off = boff0 + (unsigned)(hf*16*PITCH + kk) * 2;
        ldmx4(bh + hf*4, uWh + off);
        ldmx4(bl + hf*4, uWl + off);
      }
      // term-major: 8 independent MMAs per group, 2 groups
#pragma unroll
      for (int mi = 0; mi < 2; mi++)
#pragma unroll
        for (int ni = 0; ni < 4; ni++)
          mma_f16(c[mi][ni], a[mi], bh + ni*2);
#pragma unroll
      for (int mi = 0; mi < 2; mi++)
#pragma unroll
        for (int ni = 0; ni < 4; ni++)
          mma_f16(c[mi][ni], a[mi], bl + ni*2);
    }
  };

  const int nb = K >> 5;                 // always >= 4
  issueChunk(0, 0);  CP_COMMIT();
  issueChunk(32, 1); CP_COMMIT();
  issueChunk(64, 2); CP_COMMIT();
  for (int k = 0; k < nb; k++) {
    CP_WAIT2();
    __syncthreads();
    compute(k % 3);
    __syncthreads();
    int kn = k + 3;
    if (kn < nb) issueChunk(kn << 5, kn % 3);
    CP_COMMIT();
  }
}

#define SM_DYN64  (3 * (64*PITCH + 2*64*PITCH) * 2)     // 46080 B
#define SM_DYN128 (3 * (128*PITCH + 2*64*PITCH) * 2)    // 61440 B

// ---------------------------------------------------------------------------
// Prep kernels
// ---------------------------------------------------------------------------
__global__ void prep_a(Ptrs P) {
  int i = blockIdx.x * 256 + threadIdx.x;
  if (i < NLY * 512 * 512) {
    int l = i >> 18; int r = i & 262143; int row = r >> 9; int col = r & 511;
    {
      int cc = row, g = col >> 7, j = col & 127;
      int v = ((cc & 127) << 2) | (cc >> 7);
      float val = ((v >> 7) == g) ? P.aW2[((size_t)l*128 + j)*128 + (v & 127)] : 0.f;
      g_W2dT[l][cc][col] = val;
    }
    {
      int g = row >> 7, j = row & 127, cc = col;
      int v = ((cc & 127) << 2) | (cc >> 7);
      float val = ((v >> 7) == g) ? P.aW3[((size_t)l*128 + j)*128 + (v & 127)] : 0.f;
      g_W3d[l][row][col] = val;
    }
  }
  if (i < NLY * 256 * 256) {
    int l = i >> 16; int r = i & 65535; int c1 = r >> 8; int k = r & 255;
    g_W1T[l][k][c1] = P.aW1[(size_t)l*65536 + (size_t)c1*256 + k];
  }
}

__global__ void sp_all(Ptrs P) {
  int i = blockIdx.x * 256 + threadIdx.x;
  if (i < BB*16384)        ((half*)g_xf)[i] = __float2half_rn(P.x[i]);
  if (i < G3*128)          splitw(P.Wih0[i], ((half*)g_W0h)[i],  ((half*)g_W0l)[i]);
  if (i < (NLY-1)*G3*HH)   splitw(P.Wih[i],  ((half*)g_WihH)[i], ((half*)g_WihL)[i]);
  if (i < NLY*G3*HH)       splitw(P.Whh[i],  ((half*)g_WhhH)[i], ((half*)g_WhhL)[i]);
  if (i < NLY*256*512)     splitw(P.aW4[i],  ((half*)g_W4h)[i],  ((half*)g_W4l)[i]);
  if (i < NLY*HH)          ((half*)g_h0f)[i] = __float2half_rn(P.h0[i]);
}

__global__ void __launch_bounds__(256, 4) prep_md() {
  __shared__ __align__(16) float As[1024], Bs[1024];
  int l = blockIdx.y;
  int i = blockIdx.x;
  int m0 = (i & 7) << 6, n0 = (i >> 3) << 6;
  const float* A0 = &g_W3d[l][m0][0];
  const float* W  = &g_W2dT[l][n0][0];
  u64 acc[4][2] = {};
  gemm64(A0, A0 + 256, 512, W, 512, 512, acc, As, Bs);
  int tx = threadIdx.x & 15, ty = threadIdx.x >> 4;
#pragma unroll
  for (int r = 0; r < 4; r++) {
    float v0,v1,v2,v3;
    unpack2(acc[r][0], v0, v1); unpack2(acc[r][1], v2, v3);
    *(float4*)(&g_Md[l][m0 + ty*4 + r][n0 + tx*4]) = make_float4(v0,v1,v2,v3);
  }
}

__global__ void __launch_bounds__(256, 4) prep_p() {
  __shared__ __align__(16) float As[1024], Bs[1024];
  int l = blockIdx.y;
  int i = blockIdx.x;
  int m0 = (i & 7) << 6;
  int nt = i >> 3;
  int half_ = nt >> 2;
  const float* A0 = &g_Md[l][m0][half_ * 256];
  const float* W  = &g_W1T[l][(nt & 3) * 64][0];
  u64 acc[4][2] = {};
  gemm64(A0, A0, 512, W, 256, 256, acc, As, Bs);
  int tx = threadIdx.x & 15, ty = threadIdx.x >> 4;
#pragma unroll
  for (int r = 0; r < 4; r++) {
    float v0,v1,v2,v3;
    unpack2(acc[r][0], v0, v1); unpack2(acc[r][1], v2, v3);
    *(float4*)(&g_P[l][m0 + ty*4 + r][nt*64 + tx*4]) = make_float4(v0,v1,v2,v3);
  }
}

__global__ void sp_P() {
  int i = blockIdx.x * 256 + threadIdx.x;
  if (i < NLY*512*512) splitw(((float*)g_P)[i], ((half*)g_Ph)[i], ((half*)g_Pl)[i]);
}

// ---------------------------------------------------------------------------
// Stage 1 (tensor, 128x64 tiles): Gi = inp @ Wih^T ; Gh = h_prev @ Whh^T.
// grid(48, nA), 256 thr.
// ---------------------------------------------------------------------------
__global__ void __launch_bounds__(256) stage1_k(Ptrs P, int w, int lmin, int pp) {
  extern __shared__ __align__(16) half sm[];
  int l = lmin + blockIdx.y, ts = w - l;
  int i = blockIdx.x;
  int which = (i >= 24); i -= which * 24;
  int m0 = (i & 1) << 7, n0 = (i >> 1) << 6;
  const half *Af, *Wh, *Wl; int lda, K, ldw; float* out;
  if (!which) {
    if (l == 0) { Af = &g_xf[m0][ts*128]; lda = 16384; K = 128;
                  Wh = &g_W0h[n0][0]; Wl = &g_W0l[n0][0]; ldw = 128; }
    else        { Af = &g_hbf[pp][l-1][m0][0]; lda = HH; K = HH;
                  Wh = &g_WihH[l-1][n0][0]; Wl = &g_WihL[l-1][n0][0]; ldw = HH; }
    out = &g_Gi[l][0][0];
  } else {
    if (ts == 0) { Af = &g_h0f[l][0]; lda = 0; }
    else         { Af = &g_hbf[pp][l][m0][0]; lda = HH; }
    K = HH; Wh = &g_WhhH[l][n0][0]; Wl = &g_WhhL[l][n0][0]; ldw = HH;
    out = &g_Gh[l][0][0];
  }
  float c[2][4][4] = {};
  mma_tileb<128>(Af, Af, lda, Wh, Wl, ldw, K, c, sm);
  int lane = threadIdx.x & 31, wid = threadIdx.x >> 5;
  int wm = wid >> 1, wn = wid & 1;
#pragma unroll
  for (int mi = 0; mi < 2; mi++) {
    int r0 = m0 + wm*32 + mi*16 + (lane >> 2);
#pragma unroll
    for (int ni = 0; ni < 4; ni++) {
      int col = n0 + wn*32 + ni*8 + 2*(lane & 3);
      *(float2*)(out + (size_t)r0 * G3 + col)       = make_float2(c[mi][ni][0], c[mi][ni][1]);
      *(float2*)(out + (size_t)(r0 + 8) * G3 + col) = make_float2(c[mi][ni][2], c[mi][ni][3]);
    }
  }
}

// ---------------------------------------------------------------------------
// Stage 2: gates -> hpre (fp32 + fp16 plane), bitonic sort -> sh plane.
// ---------------------------------------------------------------------------
__global__ void __launch_bounds__(256) gatesort_k(Ptrs P, int w, int lmin, int pp) {
  int l = lmin + blockIdx.y, t = w - l;
  int warp = threadIdx.x >> 5, lane = threadIdx.x & 31;
  int b = blockIdx.x * 8 + warp;
  __shared__ float vbuf[8][256];
  float* v = vbuf[warp];
  const float* bi = P.bih + l * G3;
  const float* bh = P.bhh + l * G3;
#pragma unroll
  for (int q = 0; q < 8; q++) {
    int j = lane + (q << 5);
    float gi0 = g_Gi[l][b][j]      + bi[j];
    float gi1 = g_Gi[l][b][j+256]  + bi[j+256];
    float gi2 = g_Gi[l][b][j+512]  + bi[j+512];
    float gh0 = g_Gh[l][b][j]      + bh[j];
    float gh1 = g_Gh[l][b][j+256]  + bh[j+256];
    float gh2 = g_Gh[l][b][j+512]  + bh[j+512];
    float r = 1.f / (1.f + expf(-(gi0 + gh0)));
    float z = 1.f / (1.f + expf(-(gi1 + gh1)));
    float n = tanhf(gi2 + r * gh2);
    float hp = (t == 0) ? P.h0[l * HH + j] : g_h[pp][l][b][j];
    float hv = (1.f - z) * n + z * hp;
    g_hpre[l][b][j] = hv;
    g_hpref[l][b][j] = __float2half_rn(hv);
    v[j] = hv;
  }
  __syncwarp();
  for (int k = 2; k <= 256; k <<= 1) {
    for (int jj = k >> 1; jj > 0; jj >>= 1) {
#pragma unroll
      for (int q = 0; q < 8; q++) {
        int idx = lane + (q << 5);
        int ixj = idx ^ jj;
        if (ixj > idx) {
          float a = v[idx], cc = v[ixj];
          bool up = ((idx & k) == 0);
          if ((a > cc) == up) { v[idx] = cc; v[ixj] = a; }
        }
      }
      __syncwarp();
    }
  }
#pragma unroll
  for (int q = 0; q < 8; q++) {
    int j = lane + (q << 5);
    g_shf[l][b][j] = __float2half_rn(v[j]);
  }
}

// ---------------------------------------------------------------------------
// Stage 3 (tensor, fused a1+a2+a3): A3 = relu([hpre|sh] @ P^T). grid(32, nA)
// ---------------------------------------------------------------------------
__global__ void __launch_bounds__(128) attn_k(int lmin) {
  extern __shared__ __align__(16) half sm[];
  int l = lmin + blockIdx.y;
  int i = blockIdx.x;
  int m0 = (i & 3) << 6, n0 = (i >> 2) << 6;
  float c[2][4][4] = {};
  mma_tileb<64>(&g_hpref[l][m0][0], &g_shf[l][m0][0], 256,
                &g_Ph[l][n0][0],    &g_Pl[l][n0][0], 512, 512, c, sm);
  int lane = threadIdx.x & 31, wid = threadIdx.x >> 5;
  int wm = wid >> 1, wn = wid & 1;
#pragma unroll
  for (int mi = 0; mi < 2; mi++) {
    int r0 = m0 + wm*32 + mi*16 + (lane >> 2);
#pragma unroll
    for (int ni = 0; ni < 4; ni++) {
      int col = n0 + wn*32 + ni*8 + 2*(lane & 3);
#pragma unroll
      for (int hf = 0; hf < 2; hf++) {
        int row = r0 + hf*8;
        float v0 = fmaxf(c[mi][ni][hf*2], 0.f);
        float v1 = fmaxf(c[mi][ni][hf*2+1], 0.f);
        *(unsigned*)(&g_A3f[l][row][col]) = pack2h(v0, v1);
      }
    }
  }
}

// ---------------------------------------------------------------------------
// Stage 4 (tensor): a4 = A3 @ W4^T ; h = hpre * sigmoid(a4). grid(16, nA)
// ---------------------------------------------------------------------------
__global__ void __launch_bounds__(128) a4_k(Ptrs P, int w, int lmin, int p) {
  extern __shared__ __align__(16) half sm[];
  int l = lmin + blockIdx.y, ts = w - l;
  int i = blockIdx.x;
  int m0 = (i & 3) << 6, n0 = (i >> 2) << 6;
  float c[2][4][4] = {};
  mma_tileb<64>(&g_A3f[l][m0][0], &g_A3f[l][m0][256], 512,
                &g_W4h[l][n0][0], &g_W4l[l][n0][0], 512, 512, c, sm);
  int lane = threadIdx.x & 31, wid = threadIdx.x >> 5;
  int wm = wid >> 1, wn = wid & 1;
#pragma unroll
  for (int mi = 0; mi < 2; mi++) {
    int r0 = m0 + wm*32 + mi*16 + (lane >> 2);
#pragma unroll
    for (int ni = 0; ni < 4; ni++) {
      int col = n0 + wn*32 + ni*8 + 2*(lane & 3);
#pragma unroll
      for (int hf = 0; hf < 2; hf++) {
        int row = r0 + hf*8;
        float va = c[mi][ni][hf*2], vb = c[mi][ni][hf*2+1];
        float2 hp = *(float2*)(&g_hpre[l][row][col]);
        float h0v = hp.x * (1.f / (1.f + expf(-va)));
        float h1v = hp.y * (1.f / (1.f + expf(-vb)));
        *(float2*)(&g_h[p][l][row][col]) = make_float2(h0v, h1v);
        *(unsigned*)(&g_hbf[p][l][row][col]) = pack2h(h0v, h1v);
        if (l == NLY - 1)
          *(float2*)(P.out + (size_t)row * 32768 + (size_t)ts * 256 + col) = make_float2(h0v, h1v);
      }
    }
  }
}

// ---------------------------------------------------------------------------
__global__ void seqdec_kernel(Ptrs P) {
  int idx = blockIdx.x * blockDim.x + threadIdx.x;
  int b = idx >> 7, s = idx & 127;
  const float* e = P.out + (size_t)b * 32768 + (size_t)s * 256;
  float a1[8][4], a2[8][4], a3[8][4];
#pragma unroll
  for (int g = 0; g < 8; g++)
#pragma unroll
    for (int o = 0; o < 4; o++) {
      float sum = P.sdb1[o];
#pragma unroll
      for (int m = 0; m < 32; m++) sum += e[g*32+m] * P.sdW1[o*32+m];
      a1[g][o] = sum;
    }
#pragma unroll
  for (int i = 0; i < 8; i++)
#pragma unroll
    for (int o = 0; o < 4; o++) {
      float sum = P.sdb2[o];
#pragma unroll
      for (int j = 0; j < 4; j++) {
        int f = i*4 + j;
        sum += a1[f & 7][f >> 3] * P.sdW2[o*4+j];
      }
      a2[i][o] = sum;
    }
#pragma unroll
  for (int i = 0; i < 8; i++)
#pragma unroll
    for (int o = 0; o < 4; o++) {
      float sum = P.sdb3[o];
#pragma unroll
      for (int j = 0; j < 4; j++) {
        int f = i*4 + j;
        sum += a2[f & 7][f >> 3] * P.sdW3[o*4+j];
      }
      a3[i][o] = sum;
    }
#pragma unroll
  for (int o = 0; o < 4; o++)
#pragma unroll
    for (int wv = 0; wv < 8; wv++) {
      float sum = P.sdb4[wv];
#pragma unroll
      for (int g = 0; g < 8; g++) {
        int f = o*8 + g;
        sum += a3[f >> 2][f & 3] * P.sdW4[wv*8+g];
      }
      P.out[YSEQ_OFF + (size_t)b * 4096 + (size_t)(s*8 + wv) * 4 + o] = sum;
    }
}

// ---------------------------------------------------------------------------
__global__ void onedec_kernel(Ptrs P) {
  int b = blockIdx.x;
  __shared__ float acc[10][4];
  int tid = threadIdx.x;
  if (tid < 10) {
    int s = 118 + tid;
    const float* e = P.out + (size_t)b * 32768 + (size_t)s * 256;
    float o1[8][4], o2[8][4], o3[8][4];
#pragma unroll
    for (int g = 0; g < 8; g++)
#pragma unroll
      for (int o = 0; o < 4; o++) {
        float sum = P.odb1[o];
#pragma unroll
        for (int m = 0; m < 32; m++) sum += e[g*32+m] * P.odW1[o*32+m];
        o1[g][o] = sum;
      }
#pragma unroll
    for (int i = 0; i < 8; i++)
#pragma unroll
      for (int o = 0; o < 4; o++) {
        float sum = P.odb2[o];
#pragma unroll
        for (int j = 0; j < 4; j++) {
          int f = i*4 + j;
          sum += o1[f & 7][f >> 3] * P.odW2[o*4+j];
        }
        o2[i][o] = sum;
      }
#pragma unroll
    for (int i = 0; i < 8; i++)
#pragma unroll
      for (int o = 0; o < 4; o++) {
        float sum = P.odb3[o];
#pragma unroll
        for (int j = 0; j < 4; j++) {
          int f = i*4 + j;
          sum += o2[f & 7][f >> 3] * P.odW3[o*4+j];
        }
        o3[i][o] = fmaxf(sum, 0.f);
      }
#pragma unroll
    for (int c = 0; c < 4; c++) {
      float sum = P.odb4[c];
#pragma unroll
      for (int f = 0; f < 32; f++) sum += o3[f >> 2][f & 3] * P.odW4[c*32+f];
      acc[tid][c] = 1.f / (1.f + expf(-sum));
    }
  }
  __syncthreads();
  if (tid < 4) {
    float s = 0.f;
#pragma unroll
    for (int i = 0; i < 10; i++) s += acc[i][tid];
    P.out[YONE_OFF + (size_t)b * 4 + tid] = s * 0.1f;
  }
}

// ---------------------------------------------------------------------------
extern "C" void kernel_launch(void* const* d_in, const int* in_sizes, int n_in,
                              void* d_out, int out_size) {
  (void)in_sizes; (void)n_in; (void)out_size;
  Ptrs P;
  P.x    = (const float*)d_in[0];
  P.Wih0 = (const float*)d_in[1];
  P.Wih  = (const float*)d_in[2];
  P.Whh  = (const float*)d_in[3];
  P.bih  = (const float*)d_in[4];
  P.bhh  = (const float*)d_in[5];
  P.h0   = (const float*)d_in[6];
  P.aW1  = (const float*)d_in[7];
  P.aW2  = (const float*)d_in[8];
  P.aW3  = (const float*)d_in[9];
  P.aW4  = (const float*)d_in[10];
  P.sdW1 = (const float*)d_in[11];
  P.sdb1 = (const float*)d_in[12];
  P.sdW2 = (const float*)d_in[13];
  P.sdb2 = (const float*)d_in[14];
  P.sdW3 = (const float*)d_in[15];
  P.sdb3 = (const float*)d_in[16];
  P.sdW4 = (const float*)d_in[17];
  P.sdb4 = (const float*)d_in[18];
  P.odW1 = (const float*)d_in[19];
  P.odb1 = (const float*)d_in[20];
  P.odW2 = (const float*)d_in[21];
  P.odb2 = (const float*)d_in[22];
  P.odW3 = (const float*)d_in[23];
  P.odb3 = (const float*)d_in[24];
  P.odW4 = (const float*)d_in[25];
  P.odb4 = (const float*)d_in[26];
  P.out  = (float*)d_out;

  static int attr_done = 0;
  if (!attr_done) {
    cudaFuncSetAttribute(stage1_k, cudaFuncAttributeMaxDynamicSharedMemorySize, SM_DYN128);
    cudaFuncSetAttribute(attn_k,   cudaFuncAttributeMaxDynamicSharedMemorySize, SM_DYN64);
    cudaFuncSetAttribute(a4_k,     cudaFuncAttributeMaxDynamicSharedMemorySize, SM_DYN64);
    attr_done = 1;
  }

  prep_a<<<6144, 256>>>(P);
  sp_all<<<16384, 256>>>(P);
  prep_md<<<dim3(64, NLY), 256>>>();

  for (int w = 0; w < SS + NLY - 1; w++) {
    int lmin = w - (SS - 1); if (lmin < 0) lmin = 0;
    int lmax = (w < NLY - 1) ? w : NLY - 1;
    int nA = lmax - lmin + 1;
    int pp = (w + 1) & 1;
    int p  = w & 1;
    stage1_k<<<dim3(48, nA), 256, SM_DYN128>>>(P, w, lmin, pp);
    if (w == 0) {
      prep_p<<<dim3(64, NLY), 256>>>();
      sp_P<<<6144, 256>>>();
    }
    gatesort_k<<<dim3(32, nA), 256>>>(P, w, lmin, pp);
    attn_k<<<dim3(32, nA), 128, SM_DYN64>>>(lmin);
    a4_k<<<dim3(16, nA), 128, SM_DYN64>>>(P, w, lmin, p);
  }

  seqdec_kernel<<<128, 256>>>(P);
  onedec_kernel<<<256, 32>>>(P);
}

// round 17
// speedup vs baseline: 1.4292x; 1.2134x over previous
#include <cuda_runtime.h>
#include <cuda_fp16.h>
#include <math.h>

#define BB 256
#define HH 256
#define NLY 6
#define SS 128
#define G3 768
#define PITCH 40   // fp16 smem row pitch (conflict-free for ldmatrix)

struct Ptrs {
  const float *x, *Wih0, *Wih, *Whh, *bih, *bhh, *h0;
  const float *aW1, *aW2, *aW3, *aW4;
  const float *sdW1,*sdb1,*sdW2,*sdb2,*sdW3,*sdb3,*sdW4,*sdb4;
  const float *odW1,*odb1,*odW2,*odb2,*odW3,*odb3,*odW4,*odb4;
  float* out;
};

typedef unsigned long long u64;

// ---------------- fp32 scratch ----------------
__device__ __align__(16) float g_h[2][NLY][BB][HH];
__device__ __align__(16) float g_hpre[NLY][BB][HH];
__device__ __align__(16) float g_Gi[NLY][BB][G3];
__device__ __align__(16) float g_Gh[NLY][BB][G3];
__device__ __align__(16) float g_W2dT[NLY][512][512];
__device__ __align__(16) float g_W3d[NLY][512][512];
__device__ __align__(16) float g_W1T[NLY][256][256];
__device__ __align__(16) float g_Md[NLY][512][512];
__device__ __align__(16) float g_P[NLY][512][512];

// ---------------- fp16 planes (single plane everywhere) ----------
__device__ __align__(16) half g_xf[BB][16384];
__device__ __align__(16) half g_W0f[G3][128];
__device__ __align__(16) half g_Wihf[NLY-1][G3][HH];
__device__ __align__(16) half g_Whhf[NLY][G3][HH];
__device__ __align__(16) half g_Pf[NLY][512][512];
__device__ __align__(16) half g_W4f[NLY][256][512];
__device__ __align__(16) half g_h0f[NLY][HH];
__device__ __align__(16) half g_hbf[2][NLY][BB][HH];
__device__ __align__(16) half g_hpref[NLY][BB][HH];
__device__ __align__(16) half g_shf[NLY][BB][HH];
__device__ __align__(16) half g_A3f[NLY][BB][512];

#define YSEQ_OFF 8388608ul
#define YONE_OFF 9437184ul

// ====================== f32x2 helpers (prep GEMMs only) =====================
__device__ __forceinline__ u64 dup2(float a) {
  u64 d; unsigned ai = __float_as_uint(a);
  asm("mov.b64 %0, {%1, %1};" : "=l"(d) : "r"(ai));
  return d;
}
__device__ __forceinline__ void fma2(u64& acc, u64 a, u64 b) {
  asm("fma.rn.f32x2 %0, %1, %2, %0;" : "+l"(acc) : "l"(a), "l"(b));
}
__device__ __forceinline__ void unpack2(u64 v, float& lo, float& hi) {
  unsigned l_, h_;
  asm("mov.b64 {%0, %1}, %2;" : "=r"(l_), "=r"(h_) : "l"(v));
  lo = __uint_as_float(l_); hi = __uint_as_float(h_);
}

__device__ __forceinline__ void gemm64(
    const float* __restrict__ A0, const float* __restrict__ A1, int lda,
    const float* __restrict__ W, int ldb, int K,
    u64 acc[4][2], float* As, float* Bs)
{
  const int t = threadIdx.x;
  const int ar = t >> 2, ak = (t & 3) << 1;
  const int tx = t & 15, ty = t >> 4;
  float2 ra, rb;
  auto loadT = [&](int k0) {
    int c = k0 + ak;
    const float* base = (c < 256) ? (A0 + c) : (A1 + (c - 256));
    ra = *(const float2*)(base + (size_t)ar * lda);
    rb = *(const float2*)(W + (size_t)ar * ldb + k0 + ak);
  };
  auto storeT = [&](int buf) {
    float* as = As + buf * 512;
    float* bs = Bs + buf * 512;
    as[ak*64 + ar] = ra.x; as[(ak+1)*64 + ar] = ra.y;
    bs[ak*64 + ar] = rb.x; bs[(ak+1)*64 + ar] = rb.y;
  };
  auto compute = [&](int buf) {
    const float* as = As + buf * 512 + ty * 4;
    const float* bs = Bs + buf * 512 + tx * 4;
#pragma unroll
    for (int kk = 0; kk < 8; kk++) {
      float4 a4v = *(const float4*)(as + kk * 64);
      ulonglong2 b2 = *(const ulonglong2*)(bs + kk * 64);
      u64 ad;
      ad = dup2(a4v.x); fma2(acc[0][0], ad, b2.x); fma2(acc[0][1], ad, b2.y);
      ad = dup2(a4v.y); fma2(acc[1][0], ad, b2.x); fma2(acc[1][1], ad, b2.y);
      ad = dup2(a4v.z); fma2(acc[2][0], ad, b2.x); fma2(acc[2][1], ad, b2.y);
      ad = dup2(a4v.w); fma2(acc[3][0], ad, b2.x); fma2(acc[3][1], ad, b2.y);
    }
  };
  const int nb = K >> 3;
  loadT(0); storeT(0); __syncthreads();
  for (int kb = 1; kb < nb; kb++) {
    loadT(kb << 3);
    compute((kb - 1) & 1);
    storeT(kb & 1);
    __syncthreads();
  }
  compute((nb - 1) & 1);
}

// ====================== fp16 helpers ==================================
__device__ __forceinline__ unsigned pack2h(float a, float b) {
  __half2 h2 = __floats2half2_rn(a, b);
  return *(unsigned*)&h2;
}

// ====================== fp16 tensor-core GEMM core ========================
__device__ __forceinline__ unsigned s2u(const void* p) {
  return (unsigned)__cvta_generic_to_shared(p);
}
__device__ __forceinline__ void ldmx4(unsigned* r, unsigned a) {
  asm volatile("ldmatrix.sync.aligned.m8n8.x4.shared.b16 {%0,%1,%2,%3}, [%4];"
               : "=r"(r[0]), "=r"(r[1]), "=r"(r[2]), "=r"(r[3]) : "r"(a));
}
__device__ __forceinline__ void mma_f16(float* c, const unsigned* a, const unsigned* b) {
  asm volatile("mma.sync.aligned.m16n8k16.row.col.f32.f16.f16.f32 "
               "{%0,%1,%2,%3}, {%4,%5,%6,%7}, {%8,%9}, {%0,%1,%2,%3};"
               : "+f"(c[0]), "+f"(c[1]), "+f"(c[2]), "+f"(c[3])
               : "r"(a[0]), "r"(a[1]), "r"(a[2]), "r"(a[3]), "r"(b[0]), "r"(b[1]));
}
__device__ __forceinline__ void cpa16(unsigned dst, const void* src) {
  asm volatile("cp.async.cg.shared.global [%0], [%1], 16;" :: "r"(dst), "l"(src));
}
#define CP_COMMIT() asm volatile("cp.async.commit_group;" ::: "memory")
#define CP_WAIT2()  asm volatile("cp.async.wait_group 2;" ::: "memory")

// MT x 64 tile, 2*MT threads (MT/16 m-warps x 2 n-warps, warp = 32m x 32n).
// Pure fp16: C = A @ W. Single plane each. 3-stage cp.async pipeline over
// 32-wide K chunks; 8 independent MMAs per kk (ILP=8).
// A concat: col c<256 from Af, else A1f at c-256. lda in elems (0=broadcast).
template<int MT>
__device__ void mma_tileb(
    const half* __restrict__ Af, const half* __restrict__ A1f, int lda,
    const half* __restrict__ Wf, int ldw, int K,
    float c[2][4][4], half* sm)
{
  constexpr int APL = MT * PITCH;            // A plane elems
  constexpr int WPL = 64 * PITCH;            // W plane elems
  constexpr int BUF_E = APL + WPL;           // elems per ring buffer
  const int t = threadIdx.x;                 // 0..2*MT-1
  const int lane = t & 31, wid = t >> 5;
  const int wm = wid >> 1, wn = wid & 1;
  const int arow = lane & 15, acg = (lane >> 4) << 3;
  const int bq = lane >> 3, brr = lane & 7;
  const int bn_base = wn*32 + ((bq >> 1) << 3) + brr;
  const int bkoff = (bq & 1) << 3;
  const unsigned aoff0 = (unsigned)((wm*32 + arow) * PITCH + acg) * 2;
  const unsigned boff0 = (unsigned)(bn_base * PITCH + bkoff) * 2;
  const unsigned base = s2u(sm);

  auto issueChunk = [&](int kb, int buf) {
    unsigned sb = base + (unsigned)(buf * BUF_E) * 2;
#pragma unroll
    for (int i = 0; i < 2; i++) {              // A: MT*4 quads
      int slot = t + i * (2*MT);
      int row = slot >> 2, cg8 = (slot & 3) << 3;
      int cidx = kb + cg8;
      const half* src; int cc;
      if (cidx < 256) { src = Af;  cc = cidx; }
      else            { src = A1f; cc = cidx - 256; }
      cpa16(sb + (unsigned)(row * PITCH + cg8) * 2,
            src + (size_t)row * lda + cc);
    }
#pragma unroll
    for (int i = 0; i < 256/(2*MT); i++) {     // W: 256 quads
      int slot = t + i * (2*MT);
      int row = slot >> 2, cg8 = (slot & 3) << 3;
      cpa16(sb + (unsigned)APL*2 + (unsigned)(row * PITCH + cg8) * 2,
            Wf + (size_t)row * ldw + kb + cg8);
    }
  };
  auto compute = [&](int buf) {
    unsigned b0 = base + (unsigned)(buf * BUF_E) * 2;
    unsigned uA = b0, uW = b0 + APL*2;
#pragma unroll
    for (int kk = 0; kk < 32; kk += 16) {
      unsigned a[2][4], bw[8];
#pragma unroll
      for (int mi = 0; mi < 2; mi++)
        ldmx4(a[mi], uA + aoff0 + (unsigned)(mi*16*PITCH + kk) * 2);
#pragma unroll
      for (int hf = 0; hf < 2; hf++)
        ldmx4(bw + hf*4, uW + boff0 + (unsigned)(hf*16*PITCH + kk) * 2);
#pragma unroll
      for (int mi = 0; mi < 2; mi++)
#pragma unroll
        for (int ni = 0; ni < 4; ni++)
          mma_f16(c[mi][ni], a[mi], bw + ni*2);
    }
  };

  const int nb = K >> 5;                 // always >= 4
  issueChunk(0, 0);  CP_COMMIT();
  issueChunk(32, 1); CP_COMMIT();
  issueChunk(64, 2); CP_COMMIT();
  for (int k = 0; k < nb; k++) {
    CP_WAIT2();
    __syncthreads();
    compute(k % 3);
    __syncthreads();
    int kn = k + 3;
    if (kn < nb) issueChunk(kn << 5, kn % 3);
    CP_COMMIT();
  }
}

#define SM_DYN64  (3 * (64*PITCH + 64*PITCH) * 2)      // 30720 B
#define SM_DYN128 (3 * (128*PITCH + 64*PITCH) * 2)     // 46080 B

// ---------------------------------------------------------------------------
// Prep kernels
// ---------------------------------------------------------------------------
__global__ void prep_a(Ptrs P) {
  int i = blockIdx.x * 256 + threadIdx.x;
  if (i < NLY * 512 * 512) {
    int l = i >> 18; int r = i & 262143; int row = r >> 9; int col = r & 511;
    {
      int cc = row, g = col >> 7, j = col & 127;
      int v = ((cc & 127) << 2) | (cc >> 7);
      float val = ((v >> 7) == g) ? P.aW2[((size_t)l*128 + j)*128 + (v & 127)] : 0.f;
      g_W2dT[l][cc][col] = val;
    }
    {
      int g = row >> 7, j = row & 127, cc = col;
      int v = ((cc & 127) << 2) | (cc >> 7);
      float val = ((v >> 7) == g) ? P.aW3[((size_t)l*128 + j)*128 + (v & 127)] : 0.f;
      g_W3d[l][row][col] = val;
    }
  }
  if (i < NLY * 256 * 256) {
    int l = i >> 16; int r = i & 65535; int c1 = r >> 8; int k = r & 255;
    g_W1T[l][k][c1] = P.aW1[(size_t)l*65536 + (size_t)c1*256 + k];
  }
}

__global__ void sp_all(Ptrs P) {
  int i = blockIdx.x * 256 + threadIdx.x;
  if (i < BB*16384)        ((half*)g_xf)[i]   = __float2half_rn(P.x[i]);
  if (i < G3*128)          ((half*)g_W0f)[i]  = __float2half_rn(P.Wih0[i]);
  if (i < (NLY-1)*G3*HH)   ((half*)g_Wihf)[i] = __float2half_rn(P.Wih[i]);
  if (i < NLY*G3*HH)       ((half*)g_Whhf)[i] = __float2half_rn(P.Whh[i]);
  if (i < NLY*256*512)     ((half*)g_W4f)[i]  = __float2half_rn(P.aW4[i]);
  if (i < NLY*HH)          ((half*)g_h0f)[i]  = __float2half_rn(P.h0[i]);
}

__global__ void __launch_bounds__(256, 4) prep_md() {
  __shared__ __align__(16) float As[1024], Bs[1024];
  int l = blockIdx.y;
  int i = blockIdx.x;
  int m0 = (i & 7) << 6, n0 = (i >> 3) << 6;
  const float* A0 = &g_W3d[l][m0][0];
  const float* W  = &g_W2dT[l][n0][0];
  u64 acc[4][2] = {};
  gemm64(A0, A0 + 256, 512, W, 512, 512, acc, As, Bs);
  int tx = threadIdx.x & 15, ty = threadIdx.x >> 4;
#pragma unroll
  for (int r = 0; r < 4; r++) {
    float v0,v1,v2,v3;
    unpack2(acc[r][0], v0, v1); unpack2(acc[r][1], v2, v3);
    *(float4*)(&g_Md[l][m0 + ty*4 + r][n0 + tx*4]) = make_float4(v0,v1,v2,v3);
  }
}

__global__ void __launch_bounds__(256, 4) prep_p() {
  __shared__ __align__(16) float As[1024], Bs[1024];
  int l = blockIdx.y;
  int i = blockIdx.x;
  int m0 = (i & 7) << 6;
  int nt = i >> 3;
  int half_ = nt >> 2;
  const float* A0 = &g_Md[l][m0][half_ * 256];
  const float* W  = &g_W1T[l][(nt & 3) * 64][0];
  u64 acc[4][2] = {};
  gemm64(A0, A0, 512, W, 256, 256, acc, As, Bs);
  int tx = threadIdx.x & 15, ty = threadIdx.x >> 4;
#pragma unroll
  for (int r = 0; r < 4; r++) {
    float v0,v1,v2,v3;
    unpack2(acc[r][0], v0, v1); unpack2(acc[r][1], v2, v3);
    *(float4*)(&g_P[l][m0 + ty*4 + r][nt*64 + tx*4]) = make_float4(v0,v1,v2,v3);
  }
}

__global__ void sp_P() {
  int i = blockIdx.x * 256 + threadIdx.x;
  if (i < NLY*512*512) ((half*)g_Pf)[i] = __float2half_rn(((float*)g_P)[i]);
}

// ---------------------------------------------------------------------------
// Stage 1 (tensor, 128x64 tiles): Gi = inp @ Wih^T ; Gh = h_prev @ Whh^T.
// grid(48, nA), 256 thr.
// ---------------------------------------------------------------------------
__global__ void __launch_bounds__(256) stage1_k(Ptrs P, int w, int lmin, int pp) {
  extern __shared__ __align__(16) half sm[];
  int l = lmin + blockIdx.y, ts = w - l;
  int i = blockIdx.x;
  int which = (i >= 24); i -= which * 24;
  int m0 = (i & 1) << 7, n0 = (i >> 1) << 6;
  const half *Af, *Wf; int lda, K, ldw; float* out;
  if (!which) {
    if (l == 0) { Af = &g_xf[m0][ts*128]; lda = 16384; K = 128;
                  Wf = &g_W0f[n0][0]; ldw = 128; }
    else        { Af = &g_hbf[pp][l-1][m0][0]; lda = HH; K = HH;
                  Wf = &g_Wihf[l-1][n0][0]; ldw = HH; }
    out = &g_Gi[l][0][0];
  } else {
    if (ts == 0) { Af = &g_h0f[l][0]; lda = 0; }
    else         { Af = &g_hbf[pp][l][m0][0]; lda = HH; }
    K = HH; Wf = &g_Whhf[l][n0][0]; ldw = HH;
    out = &g_Gh[l][0][0];
  }
  float c[2][4][4] = {};
  mma_tileb<128>(Af, Af, lda, Wf, ldw, K, c, sm);
  int lane = threadIdx.x & 31, wid = threadIdx.x >> 5;
  int wm = wid >> 1, wn = wid & 1;
#pragma unroll
  for (int mi = 0; mi < 2; mi++) {
    int r0 = m0 + wm*32 + mi*16 + (lane >> 2);
#pragma unroll
    for (int ni = 0; ni < 4; ni++) {
      int col = n0 + wn*32 + ni*8 + 2*(lane & 3);
      *(float2*)(out + (size_t)r0 * G3 + col)       = make_float2(c[mi][ni][0], c[mi][ni][1]);
      *(float2*)(out + (size_t)(r0 + 8) * G3 + col) = make_float2(c[mi][ni][2], c[mi][ni][3]);
    }
  }
}

// ---------------------------------------------------------------------------
// Stage 2: gates -> hpre (fp32 + fp16 plane), bitonic sort -> sh plane.
// ---------------------------------------------------------------------------
__global__ void __launch_bounds__(256) gatesort_k(Ptrs P, int w, int lmin, int pp) {
  int l = lmin + blockIdx.y, t = w - l;
  int warp = threadIdx.x >> 5, lane = threadIdx.x & 31;
  int b = blockIdx.x * 8 + warp;
  __shared__ float vbuf[8][256];
  float* v = vbuf[warp];
  const float* bi = P.bih + l * G3;
  const float* bh = P.bhh + l * G3;
#pragma unroll
  for (int q = 0; q < 8; q++) {
    int j = lane + (q << 5);
    float gi0 = g_Gi[l][b][j]      + bi[j];
    float gi1 = g_Gi[l][b][j+256]  + bi[j+256];
    float gi2 = g_Gi[l][b][j+512]  + bi[j+512];
    float gh0 = g_Gh[l][b][j]      + bh[j];
    float gh1 = g_Gh[l][b][j+256]  + bh[j+256];
    float gh2 = g_Gh[l][b][j+512]  + bh[j+512];
    float r = 1.f / (1.f + expf(-(gi0 + gh0)));
    float z = 1.f / (1.f + expf(-(gi1 + gh1)));
    float n = tanhf(gi2 + r * gh2);
    float hp = (t == 0) ? P.h0[l * HH + j] : g_h[pp][l][b][j];
    float hv = (1.f - z) * n + z * hp;
    g_hpre[l][b][j] = hv;
    g_hpref[l][b][j] = __float2half_rn(hv);
    v[j] = hv;
  }
  __syncwarp();
  for (int k = 2; k <= 256; k <<= 1) {
    for (int jj = k >> 1; jj > 0; jj >>= 1) {
#pragma unroll
      for (int q = 0; q < 8; q++) {
        int idx = lane + (q << 5);
        int ixj = idx ^ jj;
        if (ixj > idx) {
          float a = v[idx], cc = v[ixj];
          bool up = ((idx & k) == 0);
          if ((a > cc) == up) { v[idx] = cc; v[ixj] = a; }
        }
      }
      __syncwarp();
    }
  }
#pragma unroll
  for (int q = 0; q < 8; q++) {
    int j = lane + (q << 5);
    g_shf[l][b][j] = __float2half_rn(v[j]);
  }
}

// ---------------------------------------------------------------------------
// Stage 3 (tensor, fused a1+a2+a3): A3 = relu([hpre|sh] @ P^T). grid(32, nA)
// ---------------------------------------------------------------------------
__global__ void __launch_bounds__(128) attn_k(int lmin) {
  extern __shared__ __align__(16) half sm[];
  int l = lmin + blockIdx.y;
  int i = blockIdx.x;
  int m0 = (i & 3) << 6, n0 = (i >> 2) << 6;
  float c[2][4][4] = {};
  mma_tileb<64>(&g_hpref[l][m0][0], &g_shf[l][m0][0], 256,
                &g_Pf[l][n0][0], 512, 512, c, sm);
  int lane = threadIdx.x & 31, wid = threadIdx.x >> 5;
  int wm = wid >> 1, wn = wid & 1;
#pragma unroll
  for (int mi = 0; mi < 2; mi++) {
    int r0 = m0 + wm*32 + mi*16 + (lane >> 2);
#pragma unroll
    for (int ni = 0; ni < 4; ni++) {
      int col = n0 + wn*32 + ni*8 + 2*(lane & 3);
#pragma unroll
      for (int hf = 0; hf < 2; hf++) {
        int row = r0 + hf*8;
        float v0 = fmaxf(c[mi][ni][hf*2], 0.f);
        float v1 = fmaxf(c[mi][ni][hf*2+1], 0.f);
        *(unsigned*)(&g_A3f[l][row][col]) = pack2h(v0, v1);
      }
    }
  }
}

// ---------------------------------------------------------------------------
// Stage 4 (tensor): a4 = A3 @ W4^T ; h = hpre * sigmoid(a4). grid(16, nA)
// ---------------------------------------------------------------------------
__global__ void __launch_bounds__(128) a4_k(Ptrs P, int w, int lmin, int p) {
  extern __shared__ __align__(16) half sm[];
  int l = lmin + blockIdx.y, ts = w - l;
  int i = blockIdx.x;
  int m0 = (i & 3) << 6, n0 = (i >> 2) << 6;
  float c[2][4][4] = {};
  mma_tileb<64>(&g_A3f[l][m0][0], &g_A3f[l][m0][256], 512,
                &g_W4f[l][n0][0], 512, 512, c, sm);
  int lane = threadIdx.x & 31, wid = threadIdx.x >> 5;
  int wm = wid >> 1, wn = wid & 1;
#pragma unroll
  for (int mi = 0; mi < 2; mi++) {
    int r0 = m0 + wm*32 + mi*16 + (lane >> 2);
#pragma unroll
    for (int ni = 0; ni < 4; ni++) {
      int col = n0 + wn*32 + ni*8 + 2*(lane & 3);
#pragma unroll
      for (int hf = 0; hf < 2; hf++) {
        int row = r0 + hf*8;
        float va = c[mi][ni][hf*2], vb = c[mi][ni][hf*2+1];
        float2 hp = *(float2*)(&g_hpre[l][row][col]);
        float h0v = hp.x * (1.f / (1.f + expf(-va)));
        float h1v = hp.y * (1.f / (1.f + expf(-vb)));
        *(float2*)(&g_h[p][l][row][col]) = make_float2(h0v, h1v);
        *(unsigned*)(&g_hbf[p][l][row][col]) = pack2h(h0v, h1v);
        if (l == NLY - 1)
          *(float2*)(P.out + (size_t)row * 32768 + (size_t)ts * 256 + col) = make_float2(h0v, h1v);
      }
    }
  }
}

// ---------------------------------------------------------------------------
__global__ void seqdec_kernel(Ptrs P) {
  int idx = blockIdx.x * blockDim.x + threadIdx.x;
  int b = idx >> 7, s = idx & 127;
  const float* e = P.out + (size_t)b * 32768 + (size_t)s * 256;
  float a1[8][4], a2[8][4], a3[8][4];
#pragma unroll
  for (int g = 0; g < 8; g++)
#pragma unroll
    for (int o = 0; o < 4; o++) {
      float sum = P.sdb1[o];
#pragma unroll
      for (int m = 0; m < 32; m++) sum += e[g*32+m] * P.sdW1[o*32+m];
      a1[g][o] = sum;
    }
#pragma unroll
  for (int i = 0; i < 8; i++)
#pragma unroll
    for (int o = 0; o < 4; o++) {
      float sum = P.sdb2[o];
#pragma unroll
      for (int j = 0; j < 4; j++) {
        int f = i*4 + j;
        sum += a1[f & 7][f >> 3] * P.sdW2[o*4+j];
      }
      a2[i][o] = sum;
    }
#pragma unroll
  for (int i = 0; i < 8; i++)
#pragma unroll
    for (int o = 0; o < 4; o++) {
      float sum = P.sdb3[o];
#pragma unroll
      for (int j = 0; j < 4; j++) {
        int f = i*4 + j;
        sum += a2[f & 7][f >> 3] * P.sdW3[o*4+j];
      }
      a3[i][o] = sum;
    }
#pragma unroll
  for (int o = 0; o < 4; o++)
#pragma unroll
    for (int wv = 0; wv < 8; wv++) {
      float sum = P.sdb4[wv];
#pragma unroll
      for (int g = 0; g < 8; g++) {
        int f = o*8 + g;
        sum += a3[f >> 2][f & 3] * P.sdW4[wv*8+g];
      }
      P.out[YSEQ_OFF + (size_t)b * 4096 + (size_t)(s*8 + wv) * 4 + o] = sum;
    }
}

// ---------------------------------------------------------------------------
__global__ void onedec_kernel(Ptrs P) {
  int b = blockIdx.x;
  __shared__ float acc[10][4];
  int tid = threadIdx.x;
  if (tid < 10) {
    int s = 118 + tid;
    const float* e = P.out + (size_t)b * 32768 + (size_t)s * 256;
    float o1[8][4], o2[8][4], o3[8][4];
#pragma unroll
    for (int g = 0; g < 8; g++)
#pragma unroll
      for (int o = 0; o < 4; o++) {
        float sum = P.odb1[o];
#pragma unroll
        for (int m = 0; m < 32; m++) sum += e[g*32+m] * P.odW1[o*32+m];
        o1[g][o] = sum;
      }
#pragma unroll
    for (int i = 0; i < 8; i++)
#pragma unroll
      for (int o = 0; o < 4; o++) {
        float sum = P.odb2[o];
#pragma unroll
        for (int j = 0; j < 4; j++) {
          int f = i*4 + j;
          sum += o1[f & 7][f >> 3] * P.odW2[o*4+j];
        }
        o2[i][o] = sum;
      }
#pragma unroll
    for (int i = 0; i < 8; i++)
#pragma unroll
      for (int o = 0; o < 4; o++) {
        float sum = P.odb3[o];
#pragma unroll
        for (int j = 0; j < 4; j++) {
          int f = i*4 + j;
          sum += o2[f & 7][f >> 3] * P.odW3[o*4+j];
        }
        o3[i][o] = fmaxf(sum, 0.f);
      }
#pragma unroll
    for (int c = 0; c < 4; c++) {
      float sum = P.odb4[c];
#pragma unroll
      for (int f = 0; f < 32; f++) sum += o3[f >> 2][f & 3] * P.odW4[c*32+f];
      acc[tid][c] = 1.f / (1.f + expf(-sum));
    }
  }
  __syncthreads();
  if (tid < 4) {
    float s = 0.f;
#pragma unroll
    for (int i = 0; i < 10; i++) s += acc[i][tid];
    P.out[YONE_OFF + (size_t)b * 4 + tid] = s * 0.1f;
  }
}

// ---------------------------------------------------------------------------
extern "C" void kernel_launch(void* const* d_in, const int* in_sizes, int n_in,
                              void* d_out, int out_size) {
  (void)in_sizes; (void)n_in; (void)out_size;
  Ptrs P;
  P.x    = (const float*)d_in[0];
  P.Wih0 = (const float*)d_in[1];
  P.Wih  = (const float*)d_in[2];
  P.Whh  = (const float*)d_in[3];
  P.bih  = (const float*)d_in[4];
  P.bhh  = (const float*)d_in[5];
  P.h0   = (const float*)d_in[6];
  P.aW1  = (const float*)d_in[7];
  P.aW2  = (const float*)d_in[8];
  P.aW3  = (const float*)d_in[9];
  P.aW4  = (const float*)d_in[10];
  P.sdW1 = (const float*)d_in[11];
  P.sdb1 = (const float*)d_in[12];
  P.sdW2 = (const float*)d_in[13];
  P.sdb2 = (const float*)d_in[14];
  P.sdW3 = (const float*)d_in[15];
  P.sdb3 = (const float*)d_in[16];
  P.sdW4 = (const float*)d_in[17];
  P.sdb4 = (const float*)d_in[18];
  P.odW1 = (const float*)d_in[19];
  P.odb1 = (const float*)d_in[20];
  P.odW2 = (const float*)d_in[21];
  P.odb2 = (const float*)d_in[22];
  P.odW3 = (const float*)d_in[23];
  P.odb3 = (const float*)d_in[24];
  P.odW4 = (const float*)d_in[25];
  P.odb4 = (const float*)d_in[26];
  P.out  = (float*)d_out;

  static int attr_done = 0;
  if (!attr_done) {
    cudaFuncSetAttribute(stage1_k, cudaFuncAttributeMaxDynamicSharedMemorySize, SM_DYN128);
    cudaFuncSetAttribute(attn_k,   cudaFuncAttributeMaxDynamicSharedMemorySize, SM_DYN64);
    cudaFuncSetAttribute(a4_k,     cudaFuncAttributeMaxDynamicSharedMemorySize, SM_DYN64);
    attr_done = 1;
  }

  prep_a<<<6144, 256>>>(P);
  sp_all<<<16384, 256>>>(P);
  prep_md<<<dim3(64, NLY), 256>>>();

  for (int w = 0; w < SS + NLY - 1; w++) {
    int lmin = w - (SS - 1); if (lmin < 0) lmin = 0;
    int lmax = (w < NLY - 1) ? w : NLY - 1;
    int nA = lmax - lmin + 1;
    int pp = (w + 1) & 1;
    int p  = w & 1;
    stage1_k<<<dim3(48, nA), 256, SM_DYN128>>>(P, w, lmin, pp);
    if (w == 0) {
      prep_p<<<dim3(64, NLY), 256>>>();
      sp_P<<<6144, 256>>>();
    }
    gatesort_k<<<dim3(32, nA), 256>>>(P, w, lmin, pp);
    attn_k<<<dim3(32, nA), 128, SM_DYN64>>>(lmin);
    a4_k<<<dim3(16, nA), 128, SM_DYN64>>>(P, w, lmin, p);
  }

  seqdec_kernel<<<128, 256>>>(P);
  onedec_kernel<<<256, 32>>>(P);
}